// round 8
// baseline (speedup 1.0000x reference)
#include <cuda_runtime.h>
#include <cuda_fp16.h>

#define D      128
#define EF     16
#define NMAX   50000
#define EMAX   1600000
#define NCHUNK_MAX 256   // ceil(NMAX/256) = 196 <= 256

typedef unsigned long long u64;

// ---------------- scratch (device globals; zero-init, no allocation) -------
__device__ float  g_pool[NMAX * D];      // e2n pooled edge messages
__device__ float  g_static[NMAX * D];    // e2n_pool @ W0 (pre-relu)
__device__ float  g_A[2][NMAX * D];      // static + h @ W1   (ping-pong)
__device__ __half g_Yh[2][NMAX * D];     // h @ W2, fp16      (ping-pong)
__device__ float  g_h[NMAX * D];         // h0 (only between w0 and first gemm)

__device__ int g_cnt[2][NMAX];
__device__ int g_off[2][NMAX + 1];
__device__ int g_cur[2][NMAX];
__device__ int g_csum[2][NCHUNK_MAX];
__device__ int g_coff[2][NCHUNK_MAX];
__device__ int g_permA[EMAX];            // edge ids grouped by e2n_dst
__device__ int g_permB[EMAX];            // edge_src values grouped by edge_dst

// ---------------- f32x2 packed math helpers --------------------------------
__device__ __forceinline__ u64 pack2(float x) {
    unsigned int u = __float_as_uint(x);
    u64 r;
    asm("mov.b64 %0, {%1, %2};" : "=l"(r) : "r"(u), "r"(u));
    return r;
}
__device__ __forceinline__ u64 ffma2(u64 a, u64 b, u64 c) {
    u64 d;
    asm("fma.rn.f32x2 %0, %1, %2, %3;" : "=l"(d) : "l"(a), "l"(b), "l"(c));
    return d;
}
__device__ __forceinline__ float2 unpack2(u64 v) {
    unsigned int lo, hi;
    asm("mov.b64 {%0, %1}, %2;" : "=r"(lo), "=r"(hi) : "l"(v));
    return make_float2(__uint_as_float(lo), __uint_as_float(hi));
}

// ---------------- CSR builders ---------------------------------------------
__global__ void k_zero_cnt(int n) {
    int i = blockIdx.x * blockDim.x + threadIdx.x;
    int s = gridDim.x * blockDim.x;
    for (; i < n; i += s) { g_cnt[0][i] = 0; g_cnt[1][i] = 0; }
}

__global__ void k_hist(const int* __restrict__ e2n, const int* __restrict__ ndst, int E) {
    int E4 = E >> 2;
    int i = blockIdx.x * blockDim.x + threadIdx.x;
    int s = gridDim.x * blockDim.x;
    for (; i < E4; i += s) {
        int4 a = ((const int4*)e2n)[i];
        int4 b = ((const int4*)ndst)[i];
        atomicAdd(&g_cnt[0][a.x], 1); atomicAdd(&g_cnt[0][a.y], 1);
        atomicAdd(&g_cnt[0][a.z], 1); atomicAdd(&g_cnt[0][a.w], 1);
        atomicAdd(&g_cnt[1][b.x], 1); atomicAdd(&g_cnt[1][b.y], 1);
        atomicAdd(&g_cnt[1][b.z], 1); atomicAdd(&g_cnt[1][b.w], 1);
    }
    int t = E4 * 4 + (blockIdx.x * blockDim.x + threadIdx.x);
    if (t < E) {
        atomicAdd(&g_cnt[0][e2n[t]], 1);
        atomicAdd(&g_cnt[1][ndst[t]], 1);
    }
}

__global__ void k_scan1(int n) {
    __shared__ int sh[256];
    int a = blockIdx.y;
    int i = blockIdx.x * 256 + threadIdx.x;
    sh[threadIdx.x] = (i < n) ? g_cnt[a][i] : 0;
    __syncthreads();
    for (int o = 128; o > 0; o >>= 1) {
        if (threadIdx.x < o) sh[threadIdx.x] += sh[threadIdx.x + o];
        __syncthreads();
    }
    if (threadIdx.x == 0) g_csum[a][blockIdx.x] = sh[0];
}

__global__ void k_scan2(int n, int nchunk) {
    __shared__ int sh[256];
    for (int a = 0; a < 2; a++) {
        int v = (threadIdx.x < nchunk) ? g_csum[a][threadIdx.x] : 0;
        sh[threadIdx.x] = v;
        __syncthreads();
        for (int o = 1; o < 256; o <<= 1) {
            int t = (threadIdx.x >= o) ? sh[threadIdx.x - o] : 0;
            __syncthreads();
            sh[threadIdx.x] += t;
            __syncthreads();
        }
        if (threadIdx.x < nchunk) g_coff[a][threadIdx.x] = sh[threadIdx.x] - v;
        if (threadIdx.x == 255)   g_off[a][n] = sh[255];
        __syncthreads();
    }
}

__global__ void k_scan3(int n) {
    __shared__ int sh[256];
    int a = blockIdx.y;
    int i = blockIdx.x * 256 + threadIdx.x;
    int v = (i < n) ? g_cnt[a][i] : 0;
    sh[threadIdx.x] = v;
    __syncthreads();
    for (int o = 1; o < 256; o <<= 1) {
        int t = (threadIdx.x >= o) ? sh[threadIdx.x - o] : 0;
        __syncthreads();
        sh[threadIdx.x] += t;
        __syncthreads();
    }
    if (i < n) {
        int excl = g_coff[a][blockIdx.x] + sh[threadIdx.x] - v;
        g_off[a][i] = excl;
        g_cur[a][i] = excl;
    }
}

__global__ void k_fill(const int* __restrict__ e2n, const int* __restrict__ ndst,
                       const int* __restrict__ nsrc, int E) {
    int E4 = E >> 2;
    int i = blockIdx.x * blockDim.x + threadIdx.x;
    int s = gridDim.x * blockDim.x;
    for (; i < E4; i += s) {
        int4 a = ((const int4*)e2n)[i];
        int4 b = ((const int4*)ndst)[i];
        int4 c = ((const int4*)nsrc)[i];
        int base = i * 4;
        int pa0 = atomicAdd(&g_cur[0][a.x], 1);
        int pa1 = atomicAdd(&g_cur[0][a.y], 1);
        int pa2 = atomicAdd(&g_cur[0][a.z], 1);
        int pa3 = atomicAdd(&g_cur[0][a.w], 1);
        int pb0 = atomicAdd(&g_cur[1][b.x], 1);
        int pb1 = atomicAdd(&g_cur[1][b.y], 1);
        int pb2 = atomicAdd(&g_cur[1][b.z], 1);
        int pb3 = atomicAdd(&g_cur[1][b.w], 1);
        g_permA[pa0] = base;     g_permA[pa1] = base + 1;
        g_permA[pa2] = base + 2; g_permA[pa3] = base + 3;
        g_permB[pb0] = c.x; g_permB[pb1] = c.y;
        g_permB[pb2] = c.z; g_permB[pb3] = c.w;
    }
    int t = E4 * 4 + (blockIdx.x * blockDim.x + threadIdx.x);
    if (t < E) {
        int pa = atomicAdd(&g_cur[0][e2n[t]], 1);
        g_permA[pa] = t;
        int pb = atomicAdd(&g_cur[1][ndst[t]], 1);
        g_permB[pb] = nsrc[t];
    }
}

// ---------------------------------------------------------------------------
// Per-node e2n pool. Weights in registers; edge loop unrolled x2.
__global__ void __launch_bounds__(256) k_edge_pool(
    const float* __restrict__ ef, const float* __restrict__ We, int n)
{
    int lane = threadIdx.x & 31;
    int col  = lane * 4;

    ulonglong2 w[EF];
#pragma unroll
    for (int k = 0; k < EF; k++)
        w[k] = *(const ulonglong2*)(We + k * D + col);

    int gw = (blockIdx.x * blockDim.x + threadIdx.x) >> 5;
    int nw = (gridDim.x * blockDim.x) >> 5;

    for (int d = gw; d < n; d += nw) {
        int j0 = g_off[0][d], j1 = g_off[0][d + 1];
        float a0 = 0.f, a1 = 0.f, a2 = 0.f, a3 = 0.f;

        int j = j0;
        for (; j + 2 <= j1; j += 2) {
            int e0 = g_permA[j], e1 = g_permA[j + 1];
            float f0 = (lane < EF) ? ef[(size_t)e0 * EF + lane] : 0.f;
            float f1 = (lane < EF) ? ef[(size_t)e1 * EF + lane] : 0.f;
            u64 t00 = 0ull, t01 = 0ull, t10 = 0ull, t11 = 0ull;
#pragma unroll
            for (int k = 0; k < EF; k++) {
                u64 x0 = pack2(__shfl_sync(0xffffffffu, f0, k));
                u64 x1 = pack2(__shfl_sync(0xffffffffu, f1, k));
                t00 = ffma2(x0, w[k].x, t00);
                t01 = ffma2(x0, w[k].y, t01);
                t10 = ffma2(x1, w[k].x, t10);
                t11 = ffma2(x1, w[k].y, t11);
            }
            float2 p00 = unpack2(t00), p01 = unpack2(t01);
            float2 p10 = unpack2(t10), p11 = unpack2(t11);
            a0 += fmaxf(p00.x, 0.f) + fmaxf(p10.x, 0.f);
            a1 += fmaxf(p00.y, 0.f) + fmaxf(p10.y, 0.f);
            a2 += fmaxf(p01.x, 0.f) + fmaxf(p11.x, 0.f);
            a3 += fmaxf(p01.y, 0.f) + fmaxf(p11.y, 0.f);
        }
        if (j < j1) {
            int e0 = g_permA[j];
            float f0 = (lane < EF) ? ef[(size_t)e0 * EF + lane] : 0.f;
            u64 t00 = 0ull, t01 = 0ull;
#pragma unroll
            for (int k = 0; k < EF; k++) {
                u64 x0 = pack2(__shfl_sync(0xffffffffu, f0, k));
                t00 = ffma2(x0, w[k].x, t00);
                t01 = ffma2(x0, w[k].y, t01);
            }
            float2 p00 = unpack2(t00), p01 = unpack2(t01);
            a0 += fmaxf(p00.x, 0.f);
            a1 += fmaxf(p00.y, 0.f);
            a2 += fmaxf(p01.x, 0.f);
            a3 += fmaxf(p01.y, 0.f);
        }
        *(float4*)(g_pool + (size_t)d * D + col) = make_float4(a0, a1, a2, a3);
    }
}

// ---------------------------------------------------------------------------
// static = pool @ W0 ; h0 = relu(static). Pre-packed stage (8B duplicated).
__global__ void __launch_bounds__(256) k_gemm_w0(const float* __restrict__ W, int n)
{
    extern __shared__ float sm[];
    float* sW  = sm;                          // 64 KB
    u64*   st8 = (u64*)(sm + D * D);          // 8 warps * 8 rows * D * 8B = 64 KB

    for (int i = threadIdx.x; i < D * D; i += blockDim.x) sW[i] = W[i];
    __syncthreads();

    int warp = threadIdx.x >> 5;
    int lane = threadIdx.x & 31;
    int col  = lane * 4;
    u64* st = st8 + warp * (8 * D);

    for (int r0 = blockIdx.x * 64 + warp * 8; r0 < n; r0 += gridDim.x * 64) {
        int rmax = n - r0; if (rmax > 8) rmax = 8;
#pragma unroll
        for (int rr = 0; rr < 8; rr++) {
            if (rr < rmax) {
                float4 v = *(const float4*)(g_pool + (size_t)(r0 + rr) * D + col);
                st[rr * D + col]     = pack2(v.x);
                st[rr * D + col + 1] = pack2(v.y);
                st[rr * D + col + 2] = pack2(v.z);
                st[rr * D + col + 3] = pack2(v.w);
            }
        }
        __syncwarp();

        u64 a0[8], a1[8];
#pragma unroll
        for (int rr = 0; rr < 8; rr++) { a0[rr] = 0ull; a1[rr] = 0ull; }

        for (int k = 0; k < D; k++) {
            ulonglong2 w = *(const ulonglong2*)(sW + k * D + col);
#pragma unroll
            for (int rr = 0; rr < 8; rr++) {
                u64 xx = st[rr * D + k];
                a0[rr] = ffma2(xx, w.x, a0[rr]);
                a1[rr] = ffma2(xx, w.y, a1[rr]);
            }
        }
#pragma unroll
        for (int rr = 0; rr < 8; rr++) {
            if (rr < rmax) {
                float2 p0 = unpack2(a0[rr]), p1 = unpack2(a1[rr]);
                float4 s = make_float4(p0.x, p0.y, p1.x, p1.y);
                *(float4*)(g_static + (size_t)(r0 + rr) * D + col) = s;
                *(float4*)(g_h + (size_t)(r0 + rr) * D + col) =
                    make_float4(fmaxf(s.x, 0.f), fmaxf(s.y, 0.f),
                                fmaxf(s.z, 0.f), fmaxf(s.w, 0.f));
            }
        }
        __syncwarp();
    }
}

// ---------------------------------------------------------------------------
// First-iteration GEMM: A[0] = static + h0 @ W1 ; Yh[0] = fp16(h0 @ W2).
__global__ void __launch_bounds__(256) k_gemmAB(
    const float* __restrict__ W1, const float* __restrict__ W2, int n)
{
    extern __shared__ float sm[];
    float* sW1 = sm;                          // 64 KB
    float* sW2 = sm + D * D;                  // 64 KB
    u64*   st8 = (u64*)(sm + 2 * D * D);      // 64 KB

    for (int i = threadIdx.x; i < D * D; i += blockDim.x) {
        sW1[i] = W1[i];
        sW2[i] = W2[i];
    }
    __syncthreads();

    int warp = threadIdx.x >> 5;
    int lane = threadIdx.x & 31;
    int col  = lane * 4;
    u64* st = st8 + warp * (8 * D);

    for (int r0 = blockIdx.x * 64 + warp * 8; r0 < n; r0 += gridDim.x * 64) {
        int rmax = n - r0; if (rmax > 8) rmax = 8;
#pragma unroll
        for (int rr = 0; rr < 8; rr++) {
            if (rr < rmax) {
                float4 v = *(const float4*)(g_h + (size_t)(r0 + rr) * D + col);
                st[rr * D + col]     = pack2(v.x);
                st[rr * D + col + 1] = pack2(v.y);
                st[rr * D + col + 2] = pack2(v.z);
                st[rr * D + col + 3] = pack2(v.w);
            }
        }
        __syncwarp();

        u64 a0[8], a1[8], y0[8], y1[8];
#pragma unroll
        for (int rr = 0; rr < 8; rr++) {
            a0[rr] = 0ull; a1[rr] = 0ull; y0[rr] = 0ull; y1[rr] = 0ull;
        }

        for (int k = 0; k < D; k++) {
            ulonglong2 w1 = *(const ulonglong2*)(sW1 + k * D + col);
            ulonglong2 w2 = *(const ulonglong2*)(sW2 + k * D + col);
#pragma unroll
            for (int rr = 0; rr < 8; rr++) {
                u64 xx = st[rr * D + k];
                a0[rr] = ffma2(xx, w1.x, a0[rr]);
                a1[rr] = ffma2(xx, w1.y, a1[rr]);
                y0[rr] = ffma2(xx, w2.x, y0[rr]);
                y1[rr] = ffma2(xx, w2.y, y1[rr]);
            }
        }
#pragma unroll
        for (int rr = 0; rr < 8; rr++) {
            if (rr < rmax) {
                float4 s = *(const float4*)(g_static + (size_t)(r0 + rr) * D + col);
                float2 pa0 = unpack2(a0[rr]), pa1 = unpack2(a1[rr]);
                float2 py0 = unpack2(y0[rr]), py1 = unpack2(y1[rr]);
                *(float4*)(g_A[0] + (size_t)(r0 + rr) * D + col) =
                    make_float4(s.x + pa0.x, s.y + pa0.y, s.z + pa1.x, s.w + pa1.y);
                __half2 q0 = __floats2half2_rn(py0.x, py0.y);
                __half2 q1 = __floats2half2_rn(py1.x, py1.y);
                uint2 pk;
                pk.x = *(unsigned int*)&q0;
                pk.y = *(unsigned int*)&q1;
                *(uint2*)(g_Yh[0] + (size_t)(r0 + rr) * D + col) = pk;
            }
        }
        __syncwarp();
    }
}

// ---------------------------------------------------------------------------
// Fused layer: h = relu(A_in[d] + sum Yh_in[src]);
//              A_out[d] = static[d] + h @ W1 ; Yh_out[d] = fp16(h @ W2).
// Ping-pong buffers (parity p = input index). 384 threads, packed stage,
// warps skew between gather (LSU/LTS) and GEMM (FMA) phases -> pipe overlap.
__global__ void __launch_bounds__(384) k_layer(
    const float* __restrict__ W1, const float* __restrict__ W2, int n, int p)
{
    extern __shared__ float sm[];
    float* sW1 = sm;                          // 64 KB
    float* sW2 = sm + D * D;                  // 64 KB
    u64*   st8 = (u64*)(sm + 2 * D * D);      // 12 warps * 8 rows * D * 8B = 96 KB

    for (int i = threadIdx.x; i < D * D; i += blockDim.x) {
        sW1[i] = W1[i];
        sW2[i] = W2[i];
    }
    __syncthreads();

    const float*  Ain  = g_A[p];
    const __half* Yin  = g_Yh[p];
    float*        Aout = g_A[1 - p];
    __half*       Yout = g_Yh[1 - p];

    int warp = threadIdx.x >> 5;   // 0..11
    int lane = threadIdx.x & 31;
    int col  = lane * 4;
    u64* st = st8 + warp * (8 * D);

    int ng = (n + 7) / 8;
    for (int g = blockIdx.x * 12 + warp; g < ng; g += gridDim.x * 12) {
        int r0 = g * 8;
        int rmax = n - r0; if (rmax > 8) rmax = 8;

        // ---- gather + merge phase ----
#pragma unroll 1
        for (int rr = 0; rr < rmax; rr++) {
            int d = r0 + rr;
            int j0 = g_off[1][d], j1 = g_off[1][d + 1];
            float4 acc0 = *(const float4*)(Ain + (size_t)d * D + col);
            float4 acc1 = make_float4(0.f, 0.f, 0.f, 0.f);
            float4 acc2 = make_float4(0.f, 0.f, 0.f, 0.f);
            float4 acc3 = make_float4(0.f, 0.f, 0.f, 0.f);
            int j = j0;
            for (; j + 4 <= j1; j += 4) {
                int s0 = g_permB[j],     s1 = g_permB[j + 1];
                int s2 = g_permB[j + 2], s3 = g_permB[j + 3];
                uint2 r0v = *(const uint2*)(Yin + (size_t)s0 * D + col);
                uint2 r1v = *(const uint2*)(Yin + (size_t)s1 * D + col);
                uint2 r2v = *(const uint2*)(Yin + (size_t)s2 * D + col);
                uint2 r3v = *(const uint2*)(Yin + (size_t)s3 * D + col);
                float2 f0a = __half22float2(*(__half2*)&r0v.x), f0b = __half22float2(*(__half2*)&r0v.y);
                float2 f1a = __half22float2(*(__half2*)&r1v.x), f1b = __half22float2(*(__half2*)&r1v.y);
                float2 f2a = __half22float2(*(__half2*)&r2v.x), f2b = __half22float2(*(__half2*)&r2v.y);
                float2 f3a = __half22float2(*(__half2*)&r3v.x), f3b = __half22float2(*(__half2*)&r3v.y);
                acc0.x += f0a.x; acc0.y += f0a.y; acc0.z += f0b.x; acc0.w += f0b.y;
                acc1.x += f1a.x; acc1.y += f1a.y; acc1.z += f1b.x; acc1.w += f1b.y;
                acc2.x += f2a.x; acc2.y += f2a.y; acc2.z += f2b.x; acc2.w += f2b.y;
                acc3.x += f3a.x; acc3.y += f3a.y; acc3.z += f3b.x; acc3.w += f3b.y;
            }
            for (; j < j1; j++) {
                int s0 = g_permB[j];
                uint2 r0v = *(const uint2*)(Yin + (size_t)s0 * D + col);
                float2 f0a = __half22float2(*(__half2*)&r0v.x), f0b = __half22float2(*(__half2*)&r0v.y);
                acc0.x += f0a.x; acc0.y += f0a.y; acc0.z += f0b.x; acc0.w += f0b.y;
            }
            float h0 = fmaxf(acc0.x + acc1.x + acc2.x + acc3.x, 0.f);
            float h1 = fmaxf(acc0.y + acc1.y + acc2.y + acc3.y, 0.f);
            float h2 = fmaxf(acc0.z + acc1.z + acc2.z + acc3.z, 0.f);
            float h3 = fmaxf(acc0.w + acc1.w + acc2.w + acc3.w, 0.f);
            st[rr * D + col]     = pack2(h0);
            st[rr * D + col + 1] = pack2(h1);
            st[rr * D + col + 2] = pack2(h2);
            st[rr * D + col + 3] = pack2(h3);
        }
        __syncwarp();

        // ---- GEMM phase ----
        u64 a0[8], a1[8], y0[8], y1[8];
#pragma unroll
        for (int rr = 0; rr < 8; rr++) {
            a0[rr] = 0ull; a1[rr] = 0ull; y0[rr] = 0ull; y1[rr] = 0ull;
        }
        if (rmax == 8) {
            for (int k = 0; k < D; k++) {
                ulonglong2 w1 = *(const ulonglong2*)(sW1 + k * D + col);
                ulonglong2 w2 = *(const ulonglong2*)(sW2 + k * D + col);
#pragma unroll
                for (int rr = 0; rr < 8; rr++) {
                    u64 xx = st[rr * D + k];
                    a0[rr] = ffma2(xx, w1.x, a0[rr]);
                    a1[rr] = ffma2(xx, w1.y, a1[rr]);
                    y0[rr] = ffma2(xx, w2.x, y0[rr]);
                    y1[rr] = ffma2(xx, w2.y, y1[rr]);
                }
            }
        } else {
            for (int k = 0; k < D; k++) {
                ulonglong2 w1 = *(const ulonglong2*)(sW1 + k * D + col);
                ulonglong2 w2 = *(const ulonglong2*)(sW2 + k * D + col);
                for (int rr = 0; rr < rmax; rr++) {
                    u64 xx = st[rr * D + k];
                    a0[rr] = ffma2(xx, w1.x, a0[rr]);
                    a1[rr] = ffma2(xx, w1.y, a1[rr]);
                    y0[rr] = ffma2(xx, w2.x, y0[rr]);
                    y1[rr] = ffma2(xx, w2.y, y1[rr]);
                }
            }
        }
#pragma unroll
        for (int rr = 0; rr < 8; rr++) {
            if (rr < rmax) {
                float4 s = *(const float4*)(g_static + (size_t)(r0 + rr) * D + col);
                float2 pa0 = unpack2(a0[rr]), pa1 = unpack2(a1[rr]);
                float2 py0 = unpack2(y0[rr]), py1 = unpack2(y1[rr]);
                *(float4*)(Aout + (size_t)(r0 + rr) * D + col) =
                    make_float4(s.x + pa0.x, s.y + pa0.y, s.z + pa1.x, s.w + pa1.y);
                __half2 q0 = __floats2half2_rn(py0.x, py0.y);
                __half2 q1 = __floats2half2_rn(py1.x, py1.y);
                uint2 pk;
                pk.x = *(unsigned int*)&q0;
                pk.y = *(unsigned int*)&q1;
                *(uint2*)(Yout + (size_t)(r0 + rr) * D + col) = pk;
            }
        }
        __syncwarp();
    }
}

// ---------------------------------------------------------------------------
// Final merge: out[d] = relu(A[p][d] + sum Yh[p][src])
__global__ void __launch_bounds__(256) k_spmm_merge(float* __restrict__ out, int n, int p)
{
    int lane = threadIdx.x & 31;
    int gw   = (blockIdx.x * blockDim.x + threadIdx.x) >> 5;
    int nw   = (gridDim.x * blockDim.x) >> 5;
    int col  = lane * 4;
    const float*  Ain = g_A[p];
    const __half* Yin = g_Yh[p];

    for (int d = gw; d < n; d += nw) {
        int j0 = g_off[1][d], j1 = g_off[1][d + 1];
        float4 acc0 = *(const float4*)(Ain + (size_t)d * D + col);
        float4 acc1 = make_float4(0.f, 0.f, 0.f, 0.f);
        float4 acc2 = make_float4(0.f, 0.f, 0.f, 0.f);
        float4 acc3 = make_float4(0.f, 0.f, 0.f, 0.f);

        int j = j0;
        for (; j + 4 <= j1; j += 4) {
            int s0 = g_permB[j],     s1 = g_permB[j + 1];
            int s2 = g_permB[j + 2], s3 = g_permB[j + 3];
            uint2 r0 = *(const uint2*)(Yin + (size_t)s0 * D + col);
            uint2 r1 = *(const uint2*)(Yin + (size_t)s1 * D + col);
            uint2 r2 = *(const uint2*)(Yin + (size_t)s2 * D + col);
            uint2 r3 = *(const uint2*)(Yin + (size_t)s3 * D + col);
            float2 f0a = __half22float2(*(__half2*)&r0.x), f0b = __half22float2(*(__half2*)&r0.y);
            float2 f1a = __half22float2(*(__half2*)&r1.x), f1b = __half22float2(*(__half2*)&r1.y);
            float2 f2a = __half22float2(*(__half2*)&r2.x), f2b = __half22float2(*(__half2*)&r2.y);
            float2 f3a = __half22float2(*(__half2*)&r3.x), f3b = __half22float2(*(__half2*)&r3.y);
            acc0.x += f0a.x; acc0.y += f0a.y; acc0.z += f0b.x; acc0.w += f0b.y;
            acc1.x += f1a.x; acc1.y += f1a.y; acc1.z += f1b.x; acc1.w += f1b.y;
            acc2.x += f2a.x; acc2.y += f2a.y; acc2.z += f2b.x; acc2.w += f2b.y;
            acc3.x += f3a.x; acc3.y += f3a.y; acc3.z += f3b.x; acc3.w += f3b.y;
        }
        for (; j < j1; j++) {
            int s0 = g_permB[j];
            uint2 r0 = *(const uint2*)(Yin + (size_t)s0 * D + col);
            float2 f0a = __half22float2(*(__half2*)&r0.x), f0b = __half22float2(*(__half2*)&r0.y);
            acc0.x += f0a.x; acc0.y += f0a.y; acc0.z += f0b.x; acc0.w += f0b.y;
        }
        float4 o;
        o.x = fmaxf(acc0.x + acc1.x + acc2.x + acc3.x, 0.f);
        o.y = fmaxf(acc0.y + acc1.y + acc2.y + acc3.y, 0.f);
        o.z = fmaxf(acc0.z + acc1.z + acc2.z + acc3.z, 0.f);
        o.w = fmaxf(acc0.w + acc1.w + acc2.w + acc3.w, 0.f);
        *(float4*)(out + (size_t)d * D + col) = o;
    }
}

// ---------------------------------------------------------------------------
extern "C" void kernel_launch(void* const* d_in, const int* in_sizes, int n_in,
                              void* d_out, int out_size)
{
    const float* edge_feat = (const float*)d_in[0];
    const float* W_e2l     = (const float*)d_in[1];
    const float* W0        = (const float*)d_in[2];
    const float* W1s[3] = { (const float*)d_in[3], (const float*)d_in[5], (const float*)d_in[7] };
    const float* W2s[3] = { (const float*)d_in[4], (const float*)d_in[6], (const float*)d_in[8] };
    const int* e2n_dst  = (const int*)d_in[9];
    const int* edge_src = (const int*)d_in[10];
    const int* edge_dst = (const int*)d_in[11];

    int E = in_sizes[9];
    int n = out_size / D;
    int nchunk = (n + 255) / 256;

    const int smem_w0 = (D * D) * 4 + (8 * 8 * D) * 8;                  // 128 KB
    const int smem_ab = (2 * D * D) * 4 + (8 * 8 * D) * 8;              // 192 KB
    const int smem_ly = (2 * D * D) * 4 + (12 * 8 * D) * 8;             // 224 KB
    cudaFuncSetAttribute(k_gemm_w0, cudaFuncAttributeMaxDynamicSharedMemorySize, smem_w0);
    cudaFuncSetAttribute(k_gemmAB,  cudaFuncAttributeMaxDynamicSharedMemorySize, smem_ab);
    cudaFuncSetAttribute(k_layer,   cudaFuncAttributeMaxDynamicSharedMemorySize, smem_ly);

    int node_blocks = (n + 7) / 8;     // warp per node
    int e4_blocks   = (E / 4 + 255) / 256;

    // --- CSR build ---
    k_zero_cnt<<<196, 256>>>(n);
    k_hist<<<e4_blocks, 256>>>(e2n_dst, edge_dst, E);
    dim3 sg(nchunk, 2);
    k_scan1<<<sg, 256>>>(n);
    k_scan2<<<1, 256>>>(n, nchunk);
    k_scan3<<<sg, 256>>>(n);
    k_fill<<<e4_blocks, 256>>>(e2n_dst, edge_dst, edge_src, E);

    // --- node pipeline ---
    k_edge_pool<<<node_blocks, 256>>>(edge_feat, W_e2l, n);
    k_gemm_w0<<<296, 256, smem_w0>>>(W0, n);
    k_gemmAB<<<148, 256, smem_ab>>>(W1s[0], W2s[0], n);          // -> A[0], Y[0]
    k_layer<<<148, 384, smem_ly>>>(W1s[1], W2s[1], n, 0);        // -> A[1], Y[1]
    k_layer<<<148, 384, smem_ly>>>(W1s[2], W2s[2], n, 1);        // -> A[0], Y[0]
    k_spmm_merge<<<node_blocks, 256>>>((float*)d_out, n, 0);
}

// round 9
// speedup vs baseline: 1.1163x; 1.1163x over previous
#include <cuda_runtime.h>
#include <cuda_fp16.h>

#define D      128
#define EF     16
#define NMAX   50000
#define EMAX   1600000
#define NCHUNK_MAX 256   // ceil(NMAX/256) = 196 <= 256

typedef unsigned long long u64;

// ---------------- scratch (device globals; zero-init, no allocation) -------
__device__ float  g_pool[NMAX * D];    // e2n pooled edge messages
__device__ float  g_static[NMAX * D];  // e2n_pool @ W0 (pre-relu)
__device__ float  g_A[NMAX * D];       // static + h @ W1
__device__ __half g_Yh[NMAX * D];      // h @ W2, fp16
__device__ float  g_h[NMAX * D];       // hidden state

__device__ int g_cnt[2][NMAX];
__device__ int g_off[2][NMAX + 1];
__device__ int g_cur[2][NMAX];
__device__ int g_csum[2][NCHUNK_MAX];
__device__ int g_coff[2][NCHUNK_MAX];
__device__ int g_permA[EMAX];          // edge ids grouped by e2n_dst
__device__ int g_permB[EMAX];          // edge_src values grouped by edge_dst

// ---------------- f32x2 packed math helpers --------------------------------
__device__ __forceinline__ u64 pack2(float x) {
    unsigned int u = __float_as_uint(x);
    u64 r;
    asm("mov.b64 %0, {%1, %2};" : "=l"(r) : "r"(u), "r"(u));
    return r;
}
__device__ __forceinline__ u64 ffma2(u64 a, u64 b, u64 c) {
    u64 d;
    asm("fma.rn.f32x2 %0, %1, %2, %3;" : "=l"(d) : "l"(a), "l"(b), "l"(c));
    return d;
}
__device__ __forceinline__ float2 unpack2(u64 v) {
    unsigned int lo, hi;
    asm("mov.b64 {%0, %1}, %2;" : "=r"(lo), "=r"(hi) : "l"(v));
    return make_float2(__uint_as_float(lo), __uint_as_float(hi));
}

// ---------------- CSR builders ---------------------------------------------
__global__ void k_zero_cnt(int n) {
    int i = blockIdx.x * blockDim.x + threadIdx.x;
    int s = gridDim.x * blockDim.x;
    for (; i < n; i += s) { g_cnt[0][i] = 0; g_cnt[1][i] = 0; }
}

__global__ void k_hist(const int* __restrict__ e2n, const int* __restrict__ ndst, int E) {
    int E4 = E >> 2;
    int i = blockIdx.x * blockDim.x + threadIdx.x;
    int s = gridDim.x * blockDim.x;
    for (; i < E4; i += s) {
        int4 a = ((const int4*)e2n)[i];
        int4 b = ((const int4*)ndst)[i];
        atomicAdd(&g_cnt[0][a.x], 1); atomicAdd(&g_cnt[0][a.y], 1);
        atomicAdd(&g_cnt[0][a.z], 1); atomicAdd(&g_cnt[0][a.w], 1);
        atomicAdd(&g_cnt[1][b.x], 1); atomicAdd(&g_cnt[1][b.y], 1);
        atomicAdd(&g_cnt[1][b.z], 1); atomicAdd(&g_cnt[1][b.w], 1);
    }
    int t = E4 * 4 + (blockIdx.x * blockDim.x + threadIdx.x);
    if (t < E) {
        atomicAdd(&g_cnt[0][e2n[t]], 1);
        atomicAdd(&g_cnt[1][ndst[t]], 1);
    }
}

__global__ void k_scan1(int n) {
    __shared__ int sh[256];
    int a = blockIdx.y;
    int i = blockIdx.x * 256 + threadIdx.x;
    sh[threadIdx.x] = (i < n) ? g_cnt[a][i] : 0;
    __syncthreads();
    for (int o = 128; o > 0; o >>= 1) {
        if (threadIdx.x < o) sh[threadIdx.x] += sh[threadIdx.x + o];
        __syncthreads();
    }
    if (threadIdx.x == 0) g_csum[a][blockIdx.x] = sh[0];
}

__global__ void k_scan2(int n, int nchunk) {
    __shared__ int sh[256];
    for (int a = 0; a < 2; a++) {
        int v = (threadIdx.x < nchunk) ? g_csum[a][threadIdx.x] : 0;
        sh[threadIdx.x] = v;
        __syncthreads();
        for (int o = 1; o < 256; o <<= 1) {
            int t = (threadIdx.x >= o) ? sh[threadIdx.x - o] : 0;
            __syncthreads();
            sh[threadIdx.x] += t;
            __syncthreads();
        }
        if (threadIdx.x < nchunk) g_coff[a][threadIdx.x] = sh[threadIdx.x] - v;
        if (threadIdx.x == 255)   g_off[a][n] = sh[255];
        __syncthreads();
    }
}

__global__ void k_scan3(int n) {
    __shared__ int sh[256];
    int a = blockIdx.y;
    int i = blockIdx.x * 256 + threadIdx.x;
    int v = (i < n) ? g_cnt[a][i] : 0;
    sh[threadIdx.x] = v;
    __syncthreads();
    for (int o = 1; o < 256; o <<= 1) {
        int t = (threadIdx.x >= o) ? sh[threadIdx.x - o] : 0;
        __syncthreads();
        sh[threadIdx.x] += t;
        __syncthreads();
    }
    if (i < n) {
        int excl = g_coff[a][blockIdx.x] + sh[threadIdx.x] - v;
        g_off[a][i] = excl;
        g_cur[a][i] = excl;
    }
}

__global__ void k_fill(const int* __restrict__ e2n, const int* __restrict__ ndst,
                       const int* __restrict__ nsrc, int E) {
    int E4 = E >> 2;
    int i = blockIdx.x * blockDim.x + threadIdx.x;
    int s = gridDim.x * blockDim.x;
    for (; i < E4; i += s) {
        int4 a = ((const int4*)e2n)[i];
        int4 b = ((const int4*)ndst)[i];
        int4 c = ((const int4*)nsrc)[i];
        int base = i * 4;
        int pa0 = atomicAdd(&g_cur[0][a.x], 1);
        int pa1 = atomicAdd(&g_cur[0][a.y], 1);
        int pa2 = atomicAdd(&g_cur[0][a.z], 1);
        int pa3 = atomicAdd(&g_cur[0][a.w], 1);
        int pb0 = atomicAdd(&g_cur[1][b.x], 1);
        int pb1 = atomicAdd(&g_cur[1][b.y], 1);
        int pb2 = atomicAdd(&g_cur[1][b.z], 1);
        int pb3 = atomicAdd(&g_cur[1][b.w], 1);
        g_permA[pa0] = base;     g_permA[pa1] = base + 1;
        g_permA[pa2] = base + 2; g_permA[pa3] = base + 3;
        g_permB[pb0] = c.x; g_permB[pb1] = c.y;
        g_permB[pb2] = c.z; g_permB[pb3] = c.w;
    }
    int t = E4 * 4 + (blockIdx.x * blockDim.x + threadIdx.x);
    if (t < E) {
        int pa = atomicAdd(&g_cur[0][e2n[t]], 1);
        g_permA[pa] = t;
        int pb = atomicAdd(&g_cur[1][ndst[t]], 1);
        g_permB[pb] = nsrc[t];
    }
}

// ---------------------------------------------------------------------------
// Per-node e2n pool. Weights in registers; edge loop unrolled x2.
__global__ void __launch_bounds__(256) k_edge_pool(
    const float* __restrict__ ef, const float* __restrict__ We, int n)
{
    int lane = threadIdx.x & 31;
    int col  = lane * 4;

    ulonglong2 w[EF];
#pragma unroll
    for (int k = 0; k < EF; k++)
        w[k] = *(const ulonglong2*)(We + k * D + col);

    int gw = (blockIdx.x * blockDim.x + threadIdx.x) >> 5;
    int nw = (gridDim.x * blockDim.x) >> 5;

    for (int d = gw; d < n; d += nw) {
        int j0 = g_off[0][d], j1 = g_off[0][d + 1];
        float a0 = 0.f, a1 = 0.f, a2 = 0.f, a3 = 0.f;

        int j = j0;
        for (; j + 2 <= j1; j += 2) {
            int e0 = g_permA[j], e1 = g_permA[j + 1];
            float f0 = (lane < EF) ? ef[(size_t)e0 * EF + lane] : 0.f;
            float f1 = (lane < EF) ? ef[(size_t)e1 * EF + lane] : 0.f;
            u64 t00 = 0ull, t01 = 0ull, t10 = 0ull, t11 = 0ull;
#pragma unroll
            for (int k = 0; k < EF; k++) {
                u64 x0 = pack2(__shfl_sync(0xffffffffu, f0, k));
                u64 x1 = pack2(__shfl_sync(0xffffffffu, f1, k));
                t00 = ffma2(x0, w[k].x, t00);
                t01 = ffma2(x0, w[k].y, t01);
                t10 = ffma2(x1, w[k].x, t10);
                t11 = ffma2(x1, w[k].y, t11);
            }
            float2 p00 = unpack2(t00), p01 = unpack2(t01);
            float2 p10 = unpack2(t10), p11 = unpack2(t11);
            a0 += fmaxf(p00.x, 0.f) + fmaxf(p10.x, 0.f);
            a1 += fmaxf(p00.y, 0.f) + fmaxf(p10.y, 0.f);
            a2 += fmaxf(p01.x, 0.f) + fmaxf(p11.x, 0.f);
            a3 += fmaxf(p01.y, 0.f) + fmaxf(p11.y, 0.f);
        }
        if (j < j1) {
            int e0 = g_permA[j];
            float f0 = (lane < EF) ? ef[(size_t)e0 * EF + lane] : 0.f;
            u64 t00 = 0ull, t01 = 0ull;
#pragma unroll
            for (int k = 0; k < EF; k++) {
                u64 x0 = pack2(__shfl_sync(0xffffffffu, f0, k));
                t00 = ffma2(x0, w[k].x, t00);
                t01 = ffma2(x0, w[k].y, t01);
            }
            float2 p00 = unpack2(t00), p01 = unpack2(t01);
            a0 += fmaxf(p00.x, 0.f);
            a1 += fmaxf(p00.y, 0.f);
            a2 += fmaxf(p01.x, 0.f);
            a3 += fmaxf(p01.y, 0.f);
        }
        *(float4*)(g_pool + (size_t)d * D + col) = make_float4(a0, a1, a2, a3);
    }
}

// ---------------------------------------------------------------------------
// static = pool @ W0 ; h0 = relu(static). Pre-packed u64 stage.
__global__ void __launch_bounds__(256) k_gemm_w0(const float* __restrict__ W, int n)
{
    extern __shared__ float sm[];
    float* sW  = sm;                          // 64 KB
    u64*   st8 = (u64*)(sm + D * D);          // 8 warps * 8 rows * D * 8B = 64 KB

    for (int i = threadIdx.x; i < D * D; i += blockDim.x) sW[i] = W[i];
    __syncthreads();

    int warp = threadIdx.x >> 5;
    int lane = threadIdx.x & 31;
    int col  = lane * 4;
    u64* st = st8 + warp * (8 * D);

    for (int r0 = blockIdx.x * 64 + warp * 8; r0 < n; r0 += gridDim.x * 64) {
        int rmax = n - r0; if (rmax > 8) rmax = 8;
#pragma unroll
        for (int rr = 0; rr < 8; rr++) {
            if (rr < rmax) {
                float4 v = *(const float4*)(g_pool + (size_t)(r0 + rr) * D + col);
                st[rr * D + col]     = pack2(v.x);
                st[rr * D + col + 1] = pack2(v.y);
                st[rr * D + col + 2] = pack2(v.z);
                st[rr * D + col + 3] = pack2(v.w);
            }
        }
        __syncwarp();

        u64 a0[8], a1[8];
#pragma unroll
        for (int rr = 0; rr < 8; rr++) { a0[rr] = 0ull; a1[rr] = 0ull; }

        for (int k = 0; k < D; k++) {
            ulonglong2 w = *(const ulonglong2*)(sW + k * D + col);
#pragma unroll
            for (int rr = 0; rr < 8; rr++) {
                u64 xx = st[rr * D + k];
                a0[rr] = ffma2(xx, w.x, a0[rr]);
                a1[rr] = ffma2(xx, w.y, a1[rr]);
            }
        }
#pragma unroll
        for (int rr = 0; rr < 8; rr++) {
            if (rr < rmax) {
                float2 p0 = unpack2(a0[rr]), p1 = unpack2(a1[rr]);
                float4 s = make_float4(p0.x, p0.y, p1.x, p1.y);
                *(float4*)(g_static + (size_t)(r0 + rr) * D + col) = s;
                *(float4*)(g_h + (size_t)(r0 + rr) * D + col) =
                    make_float4(fmaxf(s.x, 0.f), fmaxf(s.y, 0.f),
                                fmaxf(s.z, 0.f), fmaxf(s.w, 0.f));
            }
        }
        __syncwarp();
    }
}

// ---------------------------------------------------------------------------
// g_A = static + h @ W1 ; g_Yh = fp16(h @ W2). Pre-packed u64 stage.
__global__ void __launch_bounds__(256) k_gemmAB(
    const float* __restrict__ W1, const float* __restrict__ W2, int n)
{
    extern __shared__ float sm[];
    float* sW1 = sm;                          // 64 KB
    float* sW2 = sm + D * D;                  // 64 KB
    u64*   st8 = (u64*)(sm + 2 * D * D);      // 64 KB

    for (int i = threadIdx.x; i < D * D; i += blockDim.x) {
        sW1[i] = W1[i];
        sW2[i] = W2[i];
    }
    __syncthreads();

    int warp = threadIdx.x >> 5;
    int lane = threadIdx.x & 31;
    int col  = lane * 4;
    u64* st = st8 + warp * (8 * D);

    for (int r0 = blockIdx.x * 64 + warp * 8; r0 < n; r0 += gridDim.x * 64) {
        int rmax = n - r0; if (rmax > 8) rmax = 8;
#pragma unroll
        for (int rr = 0; rr < 8; rr++) {
            if (rr < rmax) {
                float4 v = *(const float4*)(g_h + (size_t)(r0 + rr) * D + col);
                st[rr * D + col]     = pack2(v.x);
                st[rr * D + col + 1] = pack2(v.y);
                st[rr * D + col + 2] = pack2(v.z);
                st[rr * D + col + 3] = pack2(v.w);
            }
        }
        __syncwarp();

        u64 a0[8], a1[8], y0[8], y1[8];
#pragma unroll
        for (int rr = 0; rr < 8; rr++) {
            a0[rr] = 0ull; a1[rr] = 0ull; y0[rr] = 0ull; y1[rr] = 0ull;
        }

        for (int k = 0; k < D; k++) {
            ulonglong2 w1 = *(const ulonglong2*)(sW1 + k * D + col);
            ulonglong2 w2 = *(const ulonglong2*)(sW2 + k * D + col);
#pragma unroll
            for (int rr = 0; rr < 8; rr++) {
                u64 xx = st[rr * D + k];
                a0[rr] = ffma2(xx, w1.x, a0[rr]);
                a1[rr] = ffma2(xx, w1.y, a1[rr]);
                y0[rr] = ffma2(xx, w2.x, y0[rr]);
                y1[rr] = ffma2(xx, w2.y, y1[rr]);
            }
        }
#pragma unroll
        for (int rr = 0; rr < 8; rr++) {
            if (rr < rmax) {
                float4 s = *(const float4*)(g_static + (size_t)(r0 + rr) * D + col);
                float2 pa0 = unpack2(a0[rr]), pa1 = unpack2(a1[rr]);
                float2 py0 = unpack2(y0[rr]), py1 = unpack2(y1[rr]);
                *(float4*)(g_A + (size_t)(r0 + rr) * D + col) =
                    make_float4(s.x + pa0.x, s.y + pa0.y, s.z + pa1.x, s.w + pa1.y);
                __half2 q0 = __floats2half2_rn(py0.x, py0.y);
                __half2 q1 = __floats2half2_rn(py1.x, py1.y);
                uint2 pk;
                pk.x = *(unsigned int*)&q0;
                pk.y = *(unsigned int*)&q1;
                *(uint2*)(g_Yh + (size_t)(r0 + rr) * D + col) = pk;
            }
        }
        __syncwarp();
    }
}

// ---------------------------------------------------------------------------
// Fused n2n spmm + merge: out[d] = relu(A[d] + sum_{src in N(d)} Yh[src])
__global__ void __launch_bounds__(256) k_spmm_merge(float* __restrict__ out, int n)
{
    int lane = threadIdx.x & 31;
    int gw   = (blockIdx.x * blockDim.x + threadIdx.x) >> 5;
    int nw   = (gridDim.x * blockDim.x) >> 5;
    float* dst = out ? out : g_h;   // device-side select (host g_h addr invalid)
    int col  = lane * 4;

    for (int d = gw; d < n; d += nw) {
        int j0 = g_off[1][d], j1 = g_off[1][d + 1];
        float4 acc0 = *(const float4*)(g_A + (size_t)d * D + col);
        float4 acc1 = make_float4(0.f, 0.f, 0.f, 0.f);
        float4 acc2 = make_float4(0.f, 0.f, 0.f, 0.f);
        float4 acc3 = make_float4(0.f, 0.f, 0.f, 0.f);

        int j = j0;
        for (; j + 4 <= j1; j += 4) {
            int s0 = g_permB[j],     s1 = g_permB[j + 1];
            int s2 = g_permB[j + 2], s3 = g_permB[j + 3];
            uint2 r0 = *(const uint2*)(g_Yh + (size_t)s0 * D + col);
            uint2 r1 = *(const uint2*)(g_Yh + (size_t)s1 * D + col);
            uint2 r2 = *(const uint2*)(g_Yh + (size_t)s2 * D + col);
            uint2 r3 = *(const uint2*)(g_Yh + (size_t)s3 * D + col);
            float2 f0a = __half22float2(*(__half2*)&r0.x), f0b = __half22float2(*(__half2*)&r0.y);
            float2 f1a = __half22float2(*(__half2*)&r1.x), f1b = __half22float2(*(__half2*)&r1.y);
            float2 f2a = __half22float2(*(__half2*)&r2.x), f2b = __half22float2(*(__half2*)&r2.y);
            float2 f3a = __half22float2(*(__half2*)&r3.x), f3b = __half22float2(*(__half2*)&r3.y);
            acc0.x += f0a.x; acc0.y += f0a.y; acc0.z += f0b.x; acc0.w += f0b.y;
            acc1.x += f1a.x; acc1.y += f1a.y; acc1.z += f1b.x; acc1.w += f1b.y;
            acc2.x += f2a.x; acc2.y += f2a.y; acc2.z += f2b.x; acc2.w += f2b.y;
            acc3.x += f3a.x; acc3.y += f3a.y; acc3.z += f3b.x; acc3.w += f3b.y;
        }
        for (; j < j1; j++) {
            int s0 = g_permB[j];
            uint2 r0 = *(const uint2*)(g_Yh + (size_t)s0 * D + col);
            float2 f0a = __half22float2(*(__half2*)&r0.x), f0b = __half22float2(*(__half2*)&r0.y);
            acc0.x += f0a.x; acc0.y += f0a.y; acc0.z += f0b.x; acc0.w += f0b.y;
        }
        float4 o;
        o.x = fmaxf(acc0.x + acc1.x + acc2.x + acc3.x, 0.f);
        o.y = fmaxf(acc0.y + acc1.y + acc2.y + acc3.y, 0.f);
        o.z = fmaxf(acc0.z + acc1.z + acc2.z + acc3.z, 0.f);
        o.w = fmaxf(acc0.w + acc1.w + acc2.w + acc3.w, 0.f);
        *(float4*)(dst + (size_t)d * D + col) = o;
    }
}

// ---------------------------------------------------------------------------
extern "C" void kernel_launch(void* const* d_in, const int* in_sizes, int n_in,
                              void* d_out, int out_size)
{
    const float* edge_feat = (const float*)d_in[0];
    const float* W_e2l     = (const float*)d_in[1];
    const float* W0        = (const float*)d_in[2];
    const float* W1s[3] = { (const float*)d_in[3], (const float*)d_in[5], (const float*)d_in[7] };
    const float* W2s[3] = { (const float*)d_in[4], (const float*)d_in[6], (const float*)d_in[8] };
    const int* e2n_dst  = (const int*)d_in[9];
    const int* edge_src = (const int*)d_in[10];
    const int* edge_dst = (const int*)d_in[11];

    int E = in_sizes[9];
    int n = out_size / D;
    int nchunk = (n + 255) / 256;

    const int smem_w0 = (D * D) * 4 + (8 * 8 * D) * 8;                  // 128 KB
    const int smem_ab = (2 * D * D) * 4 + (8 * 8 * D) * 8;              // 192 KB
    cudaFuncSetAttribute(k_gemm_w0, cudaFuncAttributeMaxDynamicSharedMemorySize, smem_w0);
    cudaFuncSetAttribute(k_gemmAB,  cudaFuncAttributeMaxDynamicSharedMemorySize, smem_ab);

    int node_blocks = (n + 7) / 8;     // warp per node
    int e4_blocks   = (E / 4 + 255) / 256;

    // --- CSR build ---
    k_zero_cnt<<<196, 256>>>(n);
    k_hist<<<e4_blocks, 256>>>(e2n_dst, edge_dst, E);
    dim3 sg(nchunk, 2);
    k_scan1<<<sg, 256>>>(n);
    k_scan2<<<1, 256>>>(n, nchunk);
    k_scan3<<<sg, 256>>>(n);
    k_fill<<<e4_blocks, 256>>>(e2n_dst, edge_dst, edge_src, E);

    // --- node pipeline ---
    k_edge_pool<<<node_blocks, 256>>>(edge_feat, W_e2l, n);
    k_gemm_w0<<<296, 256, smem_w0>>>(W0, n);

    for (int it = 0; it < 3; it++) {
        k_gemmAB<<<148, 256, smem_ab>>>(W1s[it], W2s[it], n);
        k_spmm_merge<<<node_blocks, 256>>>(it == 2 ? (float*)d_out : nullptr, n);
    }
}

// round 10
// speedup vs baseline: 1.2485x; 1.1185x over previous
#include <cuda_runtime.h>
#include <cuda_fp16.h>

#define D      128
#define EF     16
#define NMAX   50000
#define EMAX   1600000
#define NCHUNK_MAX 256   // ceil(NMAX/256) = 196 <= 256

typedef unsigned long long u64;

// ---------------- scratch (device globals; zero-init, no allocation) -------
__device__ float  g_pool[NMAX * D];    // e2n pooled edge messages
__device__ float  g_static[NMAX * D];  // e2n_pool @ W0 (pre-relu)
__device__ float  g_A[NMAX * D];       // static + h @ W1
__device__ __half g_Yh[NMAX * D];      // h @ W2, fp16
__device__ float  g_h[NMAX * D];       // hidden state

__device__ int g_cnt[2][NMAX];
__device__ int g_off[2][NMAX + 1];
__device__ int g_cur[2][NMAX];
__device__ int g_csum[2][NCHUNK_MAX];
__device__ int g_coff[2][NCHUNK_MAX];
__device__ int g_permA[EMAX];          // edge ids grouped by e2n_dst
__device__ int g_permB[EMAX];          // edge_src values grouped by edge_dst

// ---------------- f32x2 packed math helpers --------------------------------
__device__ __forceinline__ u64 pack2(float x) {
    unsigned int u = __float_as_uint(x);
    u64 r;
    asm("mov.b64 %0, {%1, %2};" : "=l"(r) : "r"(u), "r"(u));
    return r;
}
__device__ __forceinline__ u64 ffma2(u64 a, u64 b, u64 c) {
    u64 d;
    asm("fma.rn.f32x2 %0, %1, %2, %3;" : "=l"(d) : "l"(a), "l"(b), "l"(c));
    return d;
}
__device__ __forceinline__ float2 unpack2(u64 v) {
    unsigned int lo, hi;
    asm("mov.b64 {%0, %1}, %2;" : "=r"(lo), "=r"(hi) : "l"(v));
    return make_float2(__uint_as_float(lo), __uint_as_float(hi));
}

// ---------------- CSR builders ---------------------------------------------
__global__ void k_zero_cnt(int n) {
    int i = blockIdx.x * blockDim.x + threadIdx.x;
    int s = gridDim.x * blockDim.x;
    for (; i < n; i += s) { g_cnt[0][i] = 0; g_cnt[1][i] = 0; }
}

__global__ void k_hist(const int* __restrict__ e2n, const int* __restrict__ ndst, int E) {
    int E4 = E >> 2;
    int i = blockIdx.x * blockDim.x + threadIdx.x;
    int s = gridDim.x * blockDim.x;
    for (; i < E4; i += s) {
        int4 a = ((const int4*)e2n)[i];
        int4 b = ((const int4*)ndst)[i];
        atomicAdd(&g_cnt[0][a.x], 1); atomicAdd(&g_cnt[0][a.y], 1);
        atomicAdd(&g_cnt[0][a.z], 1); atomicAdd(&g_cnt[0][a.w], 1);
        atomicAdd(&g_cnt[1][b.x], 1); atomicAdd(&g_cnt[1][b.y], 1);
        atomicAdd(&g_cnt[1][b.z], 1); atomicAdd(&g_cnt[1][b.w], 1);
    }
    int t = E4 * 4 + (blockIdx.x * blockDim.x + threadIdx.x);
    if (t < E) {
        atomicAdd(&g_cnt[0][e2n[t]], 1);
        atomicAdd(&g_cnt[1][ndst[t]], 1);
    }
}

__global__ void k_scan1(int n) {
    __shared__ int sh[256];
    int a = blockIdx.y;
    int i = blockIdx.x * 256 + threadIdx.x;
    sh[threadIdx.x] = (i < n) ? g_cnt[a][i] : 0;
    __syncthreads();
    for (int o = 128; o > 0; o >>= 1) {
        if (threadIdx.x < o) sh[threadIdx.x] += sh[threadIdx.x + o];
        __syncthreads();
    }
    if (threadIdx.x == 0) g_csum[a][blockIdx.x] = sh[0];
}

__global__ void k_scan2(int n, int nchunk) {
    __shared__ int sh[256];
    for (int a = 0; a < 2; a++) {
        int v = (threadIdx.x < nchunk) ? g_csum[a][threadIdx.x] : 0;
        sh[threadIdx.x] = v;
        __syncthreads();
        for (int o = 1; o < 256; o <<= 1) {
            int t = (threadIdx.x >= o) ? sh[threadIdx.x - o] : 0;
            __syncthreads();
            sh[threadIdx.x] += t;
            __syncthreads();
        }
        if (threadIdx.x < nchunk) g_coff[a][threadIdx.x] = sh[threadIdx.x] - v;
        if (threadIdx.x == 255)   g_off[a][n] = sh[255];
        __syncthreads();
    }
}

__global__ void k_scan3(int n) {
    __shared__ int sh[256];
    int a = blockIdx.y;
    int i = blockIdx.x * 256 + threadIdx.x;
    int v = (i < n) ? g_cnt[a][i] : 0;
    sh[threadIdx.x] = v;
    __syncthreads();
    for (int o = 1; o < 256; o <<= 1) {
        int t = (threadIdx.x >= o) ? sh[threadIdx.x - o] : 0;
        __syncthreads();
        sh[threadIdx.x] += t;
        __syncthreads();
    }
    if (i < n) {
        int excl = g_coff[a][blockIdx.x] + sh[threadIdx.x] - v;
        g_off[a][i] = excl;
        g_cur[a][i] = excl;
    }
}

__global__ void k_fill(const int* __restrict__ e2n, const int* __restrict__ ndst,
                       const int* __restrict__ nsrc, int E) {
    int E4 = E >> 2;
    int i = blockIdx.x * blockDim.x + threadIdx.x;
    int s = gridDim.x * blockDim.x;
    for (; i < E4; i += s) {
        int4 a = ((const int4*)e2n)[i];
        int4 b = ((const int4*)ndst)[i];
        int4 c = ((const int4*)nsrc)[i];
        int base = i * 4;
        int pa0 = atomicAdd(&g_cur[0][a.x], 1);
        int pa1 = atomicAdd(&g_cur[0][a.y], 1);
        int pa2 = atomicAdd(&g_cur[0][a.z], 1);
        int pa3 = atomicAdd(&g_cur[0][a.w], 1);
        int pb0 = atomicAdd(&g_cur[1][b.x], 1);
        int pb1 = atomicAdd(&g_cur[1][b.y], 1);
        int pb2 = atomicAdd(&g_cur[1][b.z], 1);
        int pb3 = atomicAdd(&g_cur[1][b.w], 1);
        g_permA[pa0] = base;     g_permA[pa1] = base + 1;
        g_permA[pa2] = base + 2; g_permA[pa3] = base + 3;
        g_permB[pb0] = c.x; g_permB[pb1] = c.y;
        g_permB[pb2] = c.z; g_permB[pb3] = c.w;
    }
    int t = E4 * 4 + (blockIdx.x * blockDim.x + threadIdx.x);
    if (t < E) {
        int pa = atomicAdd(&g_cur[0][e2n[t]], 1);
        g_permA[pa] = t;
        int pb = atomicAdd(&g_cur[1][ndst[t]], 1);
        g_permB[pb] = nsrc[t];
    }
}

// ---------------------------------------------------------------------------
// Per-node e2n pool. Weights in registers; edge loop unrolled x2.
__global__ void __launch_bounds__(256) k_edge_pool(
    const float* __restrict__ ef, const float* __restrict__ We, int n)
{
    int lane = threadIdx.x & 31;
    int col  = lane * 4;

    ulonglong2 w[EF];
#pragma unroll
    for (int k = 0; k < EF; k++)
        w[k] = *(const ulonglong2*)(We + k * D + col);

    int gw = (blockIdx.x * blockDim.x + threadIdx.x) >> 5;
    int nw = (gridDim.x * blockDim.x) >> 5;

    for (int d = gw; d < n; d += nw) {
        int j0 = g_off[0][d], j1 = g_off[0][d + 1];
        float a0 = 0.f, a1 = 0.f, a2 = 0.f, a3 = 0.f;

        int j = j0;
        for (; j + 2 <= j1; j += 2) {
            int e0 = g_permA[j], e1 = g_permA[j + 1];
            float f0 = (lane < EF) ? ef[(size_t)e0 * EF + lane] : 0.f;
            float f1 = (lane < EF) ? ef[(size_t)e1 * EF + lane] : 0.f;
            u64 t00 = 0ull, t01 = 0ull, t10 = 0ull, t11 = 0ull;
#pragma unroll
            for (int k = 0; k < EF; k++) {
                u64 x0 = pack2(__shfl_sync(0xffffffffu, f0, k));
                u64 x1 = pack2(__shfl_sync(0xffffffffu, f1, k));
                t00 = ffma2(x0, w[k].x, t00);
                t01 = ffma2(x0, w[k].y, t01);
                t10 = ffma2(x1, w[k].x, t10);
                t11 = ffma2(x1, w[k].y, t11);
            }
            float2 p00 = unpack2(t00), p01 = unpack2(t01);
            float2 p10 = unpack2(t10), p11 = unpack2(t11);
            a0 += fmaxf(p00.x, 0.f) + fmaxf(p10.x, 0.f);
            a1 += fmaxf(p00.y, 0.f) + fmaxf(p10.y, 0.f);
            a2 += fmaxf(p01.x, 0.f) + fmaxf(p11.x, 0.f);
            a3 += fmaxf(p01.y, 0.f) + fmaxf(p11.y, 0.f);
        }
        if (j < j1) {
            int e0 = g_permA[j];
            float f0 = (lane < EF) ? ef[(size_t)e0 * EF + lane] : 0.f;
            u64 t00 = 0ull, t01 = 0ull;
#pragma unroll
            for (int k = 0; k < EF; k++) {
                u64 x0 = pack2(__shfl_sync(0xffffffffu, f0, k));
                t00 = ffma2(x0, w[k].x, t00);
                t01 = ffma2(x0, w[k].y, t01);
            }
            float2 p00 = unpack2(t00), p01 = unpack2(t01);
            a0 += fmaxf(p00.x, 0.f);
            a1 += fmaxf(p00.y, 0.f);
            a2 += fmaxf(p01.x, 0.f);
            a3 += fmaxf(p01.y, 0.f);
        }
        *(float4*)(g_pool + (size_t)d * D + col) = make_float4(a0, a1, a2, a3);
    }
}

// ---------------------------------------------------------------------------
// static = pool @ W0 ; h0 = relu(static). R7-proven form: float4 stage, 96KB,
// 2 blocks/SM (grid 296).
__global__ void __launch_bounds__(256) k_gemm_w0(const float* __restrict__ W, int n)
{
    extern __shared__ float sm[];
    float* sW    = sm;            // 64 KB
    float* stage = sm + D * D;    // 8*8*D*4 = 32 KB

    for (int i = threadIdx.x; i < D * D; i += blockDim.x) sW[i] = W[i];
    __syncthreads();

    int warp = threadIdx.x >> 5;
    int lane = threadIdx.x & 31;
    int col  = lane * 4;
    float* st = stage + warp * (8 * D);

    for (int r0 = blockIdx.x * 64 + warp * 8; r0 < n; r0 += gridDim.x * 64) {
        int rmax = n - r0; if (rmax > 8) rmax = 8;
#pragma unroll
        for (int rr = 0; rr < 8; rr++)
            if (rr < rmax)
                *(float4*)(st + rr * D + col) =
                    *(const float4*)(g_pool + (size_t)(r0 + rr) * D + col);
        __syncwarp();

        u64 a0[8], a1[8];
#pragma unroll
        for (int rr = 0; rr < 8; rr++) { a0[rr] = 0ull; a1[rr] = 0ull; }

        for (int k = 0; k < D; k++) {
            ulonglong2 w = *(const ulonglong2*)(sW + k * D + col);
#pragma unroll
            for (int rr = 0; rr < 8; rr++) {
                u64 xx = pack2(st[rr * D + k]);
                a0[rr] = ffma2(xx, w.x, a0[rr]);
                a1[rr] = ffma2(xx, w.y, a1[rr]);
            }
        }
#pragma unroll
        for (int rr = 0; rr < 8; rr++) {
            if (rr < rmax) {
                float2 p0 = unpack2(a0[rr]), p1 = unpack2(a1[rr]);
                float4 s = make_float4(p0.x, p0.y, p1.x, p1.y);
                *(float4*)(g_static + (size_t)(r0 + rr) * D + col) = s;
                *(float4*)(g_h + (size_t)(r0 + rr) * D + col) =
                    make_float4(fmaxf(s.x, 0.f), fmaxf(s.y, 0.f),
                                fmaxf(s.z, 0.f), fmaxf(s.w, 0.f));
            }
        }
        __syncwarp();
    }
}

// ---------------------------------------------------------------------------
// g_A = static + h @ W1 ; g_Yh = fp16(h @ W2).
// 512 threads (16 warps = 4/SMSP) to hide the k-loop LDS latency.
// smem: 128KB weights + 64KB stage = 192KB, 1 block/SM.
__global__ void __launch_bounds__(512) k_gemmAB(
    const float* __restrict__ W1, const float* __restrict__ W2, int n)
{
    extern __shared__ float sm[];
    float* sW1   = sm;                // 64 KB
    float* sW2   = sm + D * D;        // 64 KB
    float* stage = sm + 2 * D * D;    // 16*8*D*4 = 64 KB

    for (int i = threadIdx.x; i < D * D; i += blockDim.x) {
        sW1[i] = W1[i];
        sW2[i] = W2[i];
    }
    __syncthreads();

    int warp = threadIdx.x >> 5;     // 0..15
    int lane = threadIdx.x & 31;
    int col  = lane * 4;
    float* st = stage + warp * (8 * D);

    for (int r0 = blockIdx.x * 128 + warp * 8; r0 < n; r0 += gridDim.x * 128) {
        int rmax = n - r0; if (rmax > 8) rmax = 8;
#pragma unroll
        for (int rr = 0; rr < 8; rr++)
            if (rr < rmax)
                *(float4*)(st + rr * D + col) =
                    *(const float4*)(g_h + (size_t)(r0 + rr) * D + col);
        __syncwarp();

        u64 a0[8], a1[8], y0[8], y1[8];
#pragma unroll
        for (int rr = 0; rr < 8; rr++) {
            a0[rr] = 0ull; a1[rr] = 0ull; y0[rr] = 0ull; y1[rr] = 0ull;
        }

        for (int k = 0; k < D; k++) {
            ulonglong2 w1 = *(const ulonglong2*)(sW1 + k * D + col);
            ulonglong2 w2 = *(const ulonglong2*)(sW2 + k * D + col);
#pragma unroll
            for (int rr = 0; rr < 8; rr++) {
                u64 xx = pack2(st[rr * D + k]);
                a0[rr] = ffma2(xx, w1.x, a0[rr]);
                a1[rr] = ffma2(xx, w1.y, a1[rr]);
                y0[rr] = ffma2(xx, w2.x, y0[rr]);
                y1[rr] = ffma2(xx, w2.y, y1[rr]);
            }
        }
#pragma unroll
        for (int rr = 0; rr < 8; rr++) {
            if (rr < rmax) {
                float4 s = *(const float4*)(g_static + (size_t)(r0 + rr) * D + col);
                float2 pa0 = unpack2(a0[rr]), pa1 = unpack2(a1[rr]);
                float2 py0 = unpack2(y0[rr]), py1 = unpack2(y1[rr]);
                *(float4*)(g_A + (size_t)(r0 + rr) * D + col) =
                    make_float4(s.x + pa0.x, s.y + pa0.y, s.z + pa1.x, s.w + pa1.y);
                __half2 q0 = __floats2half2_rn(py0.x, py0.y);
                __half2 q1 = __floats2half2_rn(py1.x, py1.y);
                uint2 pk;
                pk.x = *(unsigned int*)&q0;
                pk.y = *(unsigned int*)&q1;
                *(uint2*)(g_Yh + (size_t)(r0 + rr) * D + col) = pk;
            }
        }
        __syncwarp();
    }
}

// ---------------------------------------------------------------------------
// Fused n2n spmm + merge: out[d] = relu(A[d] + sum_{src in N(d)} Yh[src])
__global__ void __launch_bounds__(256) k_spmm_merge(float* __restrict__ out, int n)
{
    int lane = threadIdx.x & 31;
    int gw   = (blockIdx.x * blockDim.x + threadIdx.x) >> 5;
    int nw   = (gridDim.x * blockDim.x) >> 5;
    float* dst = out ? out : g_h;   // device-side select (host g_h addr invalid)
    int col  = lane * 4;

    for (int d = gw; d < n; d += nw) {
        int j0 = g_off[1][d], j1 = g_off[1][d + 1];
        float4 acc0 = *(const float4*)(g_A + (size_t)d * D + col);
        float4 acc1 = make_float4(0.f, 0.f, 0.f, 0.f);
        float4 acc2 = make_float4(0.f, 0.f, 0.f, 0.f);
        float4 acc3 = make_float4(0.f, 0.f, 0.f, 0.f);

        int j = j0;
        for (; j + 4 <= j1; j += 4) {
            int s0 = g_permB[j],     s1 = g_permB[j + 1];
            int s2 = g_permB[j + 2], s3 = g_permB[j + 3];
            uint2 r0 = *(const uint2*)(g_Yh + (size_t)s0 * D + col);
            uint2 r1 = *(const uint2*)(g_Yh + (size_t)s1 * D + col);
            uint2 r2 = *(const uint2*)(g_Yh + (size_t)s2 * D + col);
            uint2 r3 = *(const uint2*)(g_Yh + (size_t)s3 * D + col);
            float2 f0a = __half22float2(*(__half2*)&r0.x), f0b = __half22float2(*(__half2*)&r0.y);
            float2 f1a = __half22float2(*(__half2*)&r1.x), f1b = __half22float2(*(__half2*)&r1.y);
            float2 f2a = __half22float2(*(__half2*)&r2.x), f2b = __half22float2(*(__half2*)&r2.y);
            float2 f3a = __half22float2(*(__half2*)&r3.x), f3b = __half22float2(*(__half2*)&r3.y);
            acc0.x += f0a.x; acc0.y += f0a.y; acc0.z += f0b.x; acc0.w += f0b.y;
            acc1.x += f1a.x; acc1.y += f1a.y; acc1.z += f1b.x; acc1.w += f1b.y;
            acc2.x += f2a.x; acc2.y += f2a.y; acc2.z += f2b.x; acc2.w += f2b.y;
            acc3.x += f3a.x; acc3.y += f3a.y; acc3.z += f3b.x; acc3.w += f3b.y;
        }
        for (; j < j1; j++) {
            int s0 = g_permB[j];
            uint2 r0 = *(const uint2*)(g_Yh + (size_t)s0 * D + col);
            float2 f0a = __half22float2(*(__half2*)&r0.x), f0b = __half22float2(*(__half2*)&r0.y);
            acc0.x += f0a.x; acc0.y += f0a.y; acc0.z += f0b.x; acc0.w += f0b.y;
        }
        float4 o;
        o.x = fmaxf(acc0.x + acc1.x + acc2.x + acc3.x, 0.f);
        o.y = fmaxf(acc0.y + acc1.y + acc2.y + acc3.y, 0.f);
        o.z = fmaxf(acc0.z + acc1.z + acc2.z + acc3.z, 0.f);
        o.w = fmaxf(acc0.w + acc1.w + acc2.w + acc3.w, 0.f);
        *(float4*)(dst + (size_t)d * D + col) = o;
    }
}

// ---------------------------------------------------------------------------
extern "C" void kernel_launch(void* const* d_in, const int* in_sizes, int n_in,
                              void* d_out, int out_size)
{
    const float* edge_feat = (const float*)d_in[0];
    const float* W_e2l     = (const float*)d_in[1];
    const float* W0        = (const float*)d_in[2];
    const float* W1s[3] = { (const float*)d_in[3], (const float*)d_in[5], (const float*)d_in[7] };
    const float* W2s[3] = { (const float*)d_in[4], (const float*)d_in[6], (const float*)d_in[8] };
    const int* e2n_dst  = (const int*)d_in[9];
    const int* edge_src = (const int*)d_in[10];
    const int* edge_dst = (const int*)d_in[11];

    int E = in_sizes[9];
    int n = out_size / D;
    int nchunk = (n + 255) / 256;

    const int smem_w0 = (D * D + 8 * 8 * D) * (int)sizeof(float);          //  96 KB
    const int smem_ab = (2 * D * D + 16 * 8 * D) * (int)sizeof(float);     // 192 KB
    cudaFuncSetAttribute(k_gemm_w0, cudaFuncAttributeMaxDynamicSharedMemorySize, smem_w0);
    cudaFuncSetAttribute(k_gemmAB,  cudaFuncAttributeMaxDynamicSharedMemorySize, smem_ab);

    int node_blocks = (n + 7) / 8;     // warp per node
    int e4_blocks   = (E / 4 + 255) / 256;

    // --- CSR build ---
    k_zero_cnt<<<196, 256>>>(n);
    k_hist<<<e4_blocks, 256>>>(e2n_dst, edge_dst, E);
    dim3 sg(nchunk, 2);
    k_scan1<<<sg, 256>>>(n);
    k_scan2<<<1, 256>>>(n, nchunk);
    k_scan3<<<sg, 256>>>(n);
    k_fill<<<e4_blocks, 256>>>(e2n_dst, edge_dst, edge_src, E);

    // --- node pipeline ---
    k_edge_pool<<<node_blocks, 256>>>(edge_feat, W_e2l, n);
    k_gemm_w0<<<296, 256, smem_w0>>>(W0, n);

    for (int it = 0; it < 3; it++) {
        k_gemmAB<<<148, 512, smem_ab>>>(W1s[it], W2s[it], n);
        k_spmm_merge<<<node_blocks, 256>>>(it == 2 ? (float*)d_out : nullptr, n);
    }
}